// round 6
// baseline (speedup 1.0000x reference)
#include <cuda_runtime.h>
#include <cstdint>

// ---------------- problem constants ----------------
#define TOKENS 8192
#define DIN    4096
#define DOUT   4096

// ---------------- quantization ----------------
// x = DELTA*q_hi + (DELTA/256)*q_lo + eps, |eps| <= DELTA/512 = 1.22e-4
#define DELTA     0.0625f        // 1/16: hi plane covers +-8 (x ~ N(0,1))
#define INV_DELTA 16.0f
#define INV_LO    4096.0f        // 256/DELTA

// ---------------- GEMM tiling ----------------
#define BM 128                 // CTA tile M
#define BN 64                  // CTA tile N
#define BK 128                 // s8 elements per K stage (128B per row)
#define STAGES 2
#define NKT (DIN / BK)         // 32 K iterations
#define NTHREADS 256           // 8 warps: 2 (m) x 4 (n), warp tile 64x16

// SMEM row stride: 128B data + 16B pad = 144B -> ldmatrix phases conflict-free.
#define STRIDE 144
#define A_HI_OFF 0
#define A_LO_OFF (BM * STRIDE)                 // 18432
#define B_OFF    (2 * BM * STRIDE)             // 36864
#define STAGE_BYTES (B_OFF + BN * STRIDE)      // 46080
#define SMEM_BYTES (STAGES * STAGE_BYTES)      // 92160 -> 2 CTAs/SM

// ---------------- device scratch ----------------
__device__ int8_t g_w8 [(size_t)DOUT   * DIN];   // 32 MB -> 16 MB; codes 0..126 EXACT in s8
__device__ int8_t g_xhi[(size_t)TOKENS * DIN];   // 32 MB
__device__ int8_t g_xlo[(size_t)TOKENS * DIN];   // 32 MB

// ---------------- PTX helpers ----------------
__device__ __forceinline__ uint32_t smem_u32(const void* p) {
    return (uint32_t)__cvta_generic_to_shared(p);
}
__device__ __forceinline__ void cp16(uint32_t s, const void* g) {
    asm volatile("cp.async.cg.shared.global [%0], [%1], 16;" :: "r"(s), "l"(g));
}
__device__ __forceinline__ void cp_commit() {
    asm volatile("cp.async.commit_group;" ::: "memory");
}
template <int N>
__device__ __forceinline__ void cp_wait() {
    asm volatile("cp.async.wait_group %0;" :: "n"(N) : "memory");
}
__device__ __forceinline__ void ldsm4(uint32_t* r, uint32_t addr) {
    asm volatile("ldmatrix.sync.aligned.m8n8.x4.shared.b16 {%0,%1,%2,%3}, [%4];"
                 : "=r"(r[0]), "=r"(r[1]), "=r"(r[2]), "=r"(r[3]) : "r"(addr));
}
// s8 IMMA, exact s32 accumulate, K=32 per instruction
__device__ __forceinline__ void imma16832(int* d, const uint32_t* a, const uint32_t* b) {
    asm volatile(
        "mma.sync.aligned.m16n8k32.row.col.s32.s8.s8.s32 "
        "{%0,%1,%2,%3}, {%4,%5,%6,%7}, {%8,%9}, {%0,%1,%2,%3};"
        : "+r"(d[0]), "+r"(d[1]), "+r"(d[2]), "+r"(d[3])
        : "r"(a[0]), "r"(a[1]), "r"(a[2]), "r"(a[3]), "r"(b[0]), "r"(b[1]));
}

// ---------------- fused conversion kernel ----------------
#define XN4 (TOKENS * DIN / 4)
#define WN4 (DOUT * DIN / 4)

__device__ __forceinline__ int8_t clamp8(int v) {
    return (int8_t)max(-128, min(127, v));
}

__global__ void convert_all_kernel(const float4* __restrict__ x,
                                   const float4* __restrict__ w) {
    int i = blockIdx.x * blockDim.x + threadIdx.x;
    if (i < XN4) {
        float4 v = x[i];
        char4 h, l;
        {
            int q = __float2int_rn(v.x * INV_DELTA); h.x = clamp8(q);
            l.x = clamp8(__float2int_rn((v.x - (float)q * DELTA) * INV_LO));
            q = __float2int_rn(v.y * INV_DELTA);     h.y = clamp8(q);
            l.y = clamp8(__float2int_rn((v.y - (float)q * DELTA) * INV_LO));
            q = __float2int_rn(v.z * INV_DELTA);     h.z = clamp8(q);
            l.z = clamp8(__float2int_rn((v.z - (float)q * DELTA) * INV_LO));
            q = __float2int_rn(v.w * INV_DELTA);     h.w = clamp8(q);
            l.w = clamp8(__float2int_rn((v.w - (float)q * DELTA) * INV_LO));
        }
        reinterpret_cast<char4*>(g_xhi)[i] = h;
        reinterpret_cast<char4*>(g_xlo)[i] = l;
    } else {
        int j = i - XN4;
        float4 v = w[j];
        char4 c;
        c.x = (int8_t)__float2int_rn(v.x);   // exact: integer codes 0..126
        c.y = (int8_t)__float2int_rn(v.y);
        c.z = (int8_t)__float2int_rn(v.z);
        c.w = (int8_t)__float2int_rn(v.w);
        reinterpret_cast<char4*>(g_w8)[j] = c;
    }
}

// ---------------- main GEMM ----------------
__global__ void __launch_bounds__(NTHREADS, 2)
gemm_kernel(const float* __restrict__ bias, const float* __restrict__ scale,
            float* __restrict__ out) {
    extern __shared__ char dsm[];
    const uint32_t base = smem_u32(dsm);

    const int tid  = threadIdx.x;
    const int lane = tid & 31;
    const int wrp  = tid >> 5;                 // 8 warps: 2 (m) x 4 (n)
    const int wm   = (wrp >> 2) * 64;          // warp m offset (0/64)
    const int wn   = (wrp & 3) * 16;           // warp n offset (0/16/32/48)
    const int gn0  = blockIdx.x * BN;
    const int gm0  = blockIdx.y * BM;

    // ---- per-thread cp.async state (advance src by BK=128 bytes per stage) ----
    const int lrowc = tid >> 3;                // 0..31
    const int lseg  = tid & 7;                 // 16B segment
    const char* ahsrc = (const char*)(g_xhi + (size_t)(gm0 + lrowc) * DIN) + lseg * 16;
    const char* alsrc = (const char*)(g_xlo + (size_t)(gm0 + lrowc) * DIN) + lseg * 16;
    const char* bsrc  = (const char*)(g_w8  + (size_t)(gn0 + lrowc) * DIN) + lseg * 16;
    const uint32_t ahdst = base + A_HI_OFF + lrowc * STRIDE + lseg * 16;
    const uint32_t aldst = base + A_LO_OFF + lrowc * STRIDE + lseg * 16;
    const uint32_t bdst  = base + B_OFF    + lrowc * STRIDE + lseg * 16;

    #define LOAD_STAGE(slot)                                                       \
        do {                                                                       \
            const uint32_t so = (slot) * STAGE_BYTES;                              \
            _Pragma("unroll")                                                      \
            for (int t = 0; t < 4; t++) {                                          \
                cp16(ahdst + so + t * (32 * STRIDE), ahsrc + (size_t)t * 32 * DIN);\
                cp16(aldst + so + t * (32 * STRIDE), alsrc + (size_t)t * 32 * DIN);\
            }                                                                      \
            _Pragma("unroll")                                                      \
            for (int t = 0; t < 2; t++)                                            \
                cp16(bdst + so + t * (32 * STRIDE), bsrc + (size_t)t * 32 * DIN);  \
            cp_commit();                                                           \
        } while (0)

    const int lrow = lane & 15;
    const int lcol = (lane >> 4) * 16;

    int acch[4][2][4], accl[4][2][4];
#pragma unroll
    for (int mi = 0; mi < 4; mi++)
#pragma unroll
        for (int ni = 0; ni < 2; ni++)
#pragma unroll
            for (int c = 0; c < 4; c++) { acch[mi][ni][c] = 0; accl[mi][ni][c] = 0; }

    // prologue
    LOAD_STAGE(0);
    ahsrc += BK; alsrc += BK; bsrc += BK;

    for (int kt = 0; kt < NKT; kt++) {
        cp_wait<0>();            // stage kt resident
        __syncthreads();

        if (kt + 1 < NKT) {
            LOAD_STAGE((kt + 1) & 1);
            ahsrc += BK; alsrc += BK; bsrc += BK;
        }

        const uint32_t st = base + (kt & 1) * STAGE_BYTES;
        const uint32_t ah_base = st + A_HI_OFF + (wm + lrow) * STRIDE + lcol;
        const uint32_t al_base = st + A_LO_OFF + (wm + lrow) * STRIDE + lcol;
        const uint32_t b_base  = st + B_OFF    + (wn + lrow) * STRIDE + lcol;

#pragma unroll
        for (int ks = 0; ks < 4; ks++) {            // four k32 sub-steps per stage
            // B: n16 x k32 -> two n8 fragments, shared by both planes
            uint32_t t4[4];
            ldsm4(t4, b_base + ks * 32);
            uint32_t b0[2] = {t4[0], t4[2]};
            uint32_t b1[2] = {t4[1], t4[3]};

            uint32_t a[4][4];
#pragma unroll
            for (int mi = 0; mi < 4; mi++)
                ldsm4(a[mi], ah_base + mi * 16 * STRIDE + ks * 32);
#pragma unroll
            for (int mi = 0; mi < 4; mi++) {
                imma16832(acch[mi][0], a[mi], b0);
                imma16832(acch[mi][1], a[mi], b1);
            }
#pragma unroll
            for (int mi = 0; mi < 4; mi++)
                ldsm4(a[mi], al_base + mi * 16 * STRIDE + ks * 32);
#pragma unroll
            for (int mi = 0; mi < 4; mi++) {
                imma16832(accl[mi][0], a[mi], b0);
                imma16832(accl[mi][1], a[mi], b1);
            }
        }
        __syncthreads();
    }

    // ---------------- epilogue: y = scale*(DELTA*Shi + DELTA/256*Slo) + bias ----
    const float sd = __ldg(scale) * DELTA;
    const float r0f = 1.0f / 256.0f;
    const int r0 = lane >> 2;
    const int c0 = 2 * (lane & 3);

#pragma unroll
    for (int ni = 0; ni < 2; ni++) {
        const int col = gn0 + wn + ni * 8 + c0;
        const float2 bv = *reinterpret_cast<const float2*>(bias + col);
#pragma unroll
        for (int mi = 0; mi < 4; mi++) {
            const int row = gm0 + wm + mi * 16 + r0;
            float2 o0, o1;
            o0.x = ((float)acch[mi][ni][0] + (float)accl[mi][ni][0] * r0f) * sd + bv.x;
            o0.y = ((float)acch[mi][ni][1] + (float)accl[mi][ni][1] * r0f) * sd + bv.y;
            o1.x = ((float)acch[mi][ni][2] + (float)accl[mi][ni][2] * r0f) * sd + bv.x;
            o1.y = ((float)acch[mi][ni][3] + (float)accl[mi][ni][3] * r0f) * sd + bv.y;
            *reinterpret_cast<float2*>(out + (size_t)row * DOUT + col)       = o0;
            *reinterpret_cast<float2*>(out + (size_t)(row + 8) * DOUT + col) = o1;
        }
    }
}

// ---------------- launch ----------------
extern "C" void kernel_launch(void* const* d_in, const int* in_sizes, int n_in,
                              void* d_out, int out_size) {
    const float* x     = (const float*)d_in[0];
    const float* w     = (const float*)d_in[1];
    const float* bias  = (const float*)d_in[2];
    const float* scale = (const float*)d_in[3];
    float* out = (float*)d_out;

    convert_all_kernel<<<(XN4 + WN4) / 256, 256>>>((const float4*)x, (const float4*)w);

    cudaFuncSetAttribute(gemm_kernel, cudaFuncAttributeMaxDynamicSharedMemorySize, SMEM_BYTES);
    dim3 grid(DOUT / BN, TOKENS / BM);   // (64, 64)
    gemm_kernel<<<grid, NTHREADS, SMEM_BYTES>>>(bias, scale, out);
}

// round 7
// speedup vs baseline: 3.2078x; 3.2078x over previous
#include <cuda_runtime.h>
#include <cuda_fp16.h>
#include <cstdint>

// ---------------- problem constants ----------------
#define TOKENS 8192
#define DIN    4096
#define DOUT   4096

// ---------------- GEMM tiling ----------------
#define BM 128                 // CTA tile M
#define BN 64                  // CTA tile N
#define BK 64                  // fp16 elements per K stage (128B per row)
#define STAGES 2
#define NKT (DIN / BK)         // 64 K iterations
#define NTHREADS 256           // 8 warps: 2 (m) x 4 (n), warp tile 64x16

// SMEM row stride: 128B data + 16B pad = 144B -> ldmatrix phases conflict-free.
#define STRIDE 144
#define A_OFF 0
#define A_BYTES (BM * STRIDE)            // 18432
#define B_OFF A_BYTES
#define B_BYTES (BN * STRIDE)            // 9216
#define STAGE_BYTES (A_BYTES + B_BYTES)  // 27648
#define SMEM_BYTES (STAGES * STAGE_BYTES)// 55296

// ---------------- device scratch ----------------
__device__ __half g_w[(size_t)DOUT   * DIN];   // 32 MB; codes 0..126 EXACT in fp16
__device__ __half g_x[(size_t)TOKENS * DIN];   // 64 MB; rel err <= 2^-11/element

// ---------------- PTX helpers ----------------
__device__ __forceinline__ uint32_t smem_u32(const void* p) {
    return (uint32_t)__cvta_generic_to_shared(p);
}
__device__ __forceinline__ void cp16(uint32_t s, const void* g) {
    asm volatile("cp.async.cg.shared.global [%0], [%1], 16;" :: "r"(s), "l"(g));
}
__device__ __forceinline__ void cp_commit() {
    asm volatile("cp.async.commit_group;" ::: "memory");
}
template <int N>
__device__ __forceinline__ void cp_wait() {
    asm volatile("cp.async.wait_group %0;" :: "n"(N) : "memory");
}
__device__ __forceinline__ void ldsm4(uint32_t* r, uint32_t addr) {
    asm volatile("ldmatrix.sync.aligned.m8n8.x4.shared.b16 {%0,%1,%2,%3}, [%4];"
                 : "=r"(r[0]), "=r"(r[1]), "=r"(r[2]), "=r"(r[3]) : "r"(addr));
}
// fp16-ACCUMULATE HMMA: the full-rate probe. D,C are 2 x f16x2 regs.
__device__ __forceinline__ void mma16816_h(uint32_t* d, const uint32_t* a, const uint32_t* b) {
    asm volatile(
        "mma.sync.aligned.m16n8k16.row.col.f16.f16.f16.f16 "
        "{%0,%1}, {%2,%3,%4,%5}, {%6,%7}, {%0,%1};"
        : "+r"(d[0]), "+r"(d[1])
        : "r"(a[0]), "r"(a[1]), "r"(a[2]), "r"(a[3]), "r"(b[0]), "r"(b[1]));
}

// ---------------- fused conversion kernel ----------------
#define XN4 (TOKENS * DIN / 4)
#define WN4 (DOUT * DIN / 4)

__global__ void convert_all_kernel(const float4* __restrict__ x,
                                   const float4* __restrict__ w) {
    int i = blockIdx.x * blockDim.x + threadIdx.x;
    if (i < XN4) {
        float4 v = x[i];
        reinterpret_cast<__half2*>(g_x)[2 * i + 0] = __floats2half2_rn(v.x, v.y);
        reinterpret_cast<__half2*>(g_x)[2 * i + 1] = __floats2half2_rn(v.z, v.w);
    } else {
        int j = i - XN4;
        float4 v = w[j];
        reinterpret_cast<__half2*>(g_w)[2 * j + 0] = __floats2half2_rn(v.x, v.y);
        reinterpret_cast<__half2*>(g_w)[2 * j + 1] = __floats2half2_rn(v.z, v.w);
    }
}

// ---------------- main GEMM ----------------
__global__ void __launch_bounds__(NTHREADS, 2)
gemm_kernel(const float* __restrict__ bias, const float* __restrict__ scale,
            float* __restrict__ out) {
    extern __shared__ char dsm[];
    const uint32_t base = smem_u32(dsm);

    const int tid  = threadIdx.x;
    const int lane = tid & 31;
    const int wrp  = tid >> 5;                 // 8 warps: 2 (m) x 4 (n)
    const int wm   = (wrp >> 2) * 64;          // warp m offset (0/64)
    const int wn   = (wrp & 3) * 16;           // warp n offset (0/16/32/48)
    const int gn0  = blockIdx.x * BN;
    const int gm0  = blockIdx.y * BM;

    // ---- per-thread cp.async state (advance src by 128B per stage) ----
    const int lrowc = tid >> 3;
    const int lseg  = tid & 7;
    const char* asrc = (const char*)(g_x + (size_t)(gm0 + lrowc) * DIN + lseg * 8);
    const char* bsrc = (const char*)(g_w + (size_t)(gn0 + lrowc) * DIN + lseg * 8);
    const uint32_t adst = base + A_OFF + lrowc * STRIDE + lseg * 16;
    const uint32_t bdst = base + B_OFF + lrowc * STRIDE + lseg * 16;

    #define LOAD_STAGE(slot)                                                        \
        do {                                                                        \
            const uint32_t so = (slot) * STAGE_BYTES;                               \
            _Pragma("unroll")                                                       \
            for (int t = 0; t < 4; t++)                                             \
                cp16(adst + so + t * (32 * STRIDE),                                 \
                     asrc + (size_t)t * (32 * DIN * 2));                            \
            _Pragma("unroll")                                                       \
            for (int t = 0; t < 2; t++)                                             \
                cp16(bdst + so + t * (32 * STRIDE),                                 \
                     bsrc + (size_t)t * (32 * DIN * 2));                            \
            cp_commit();                                                            \
        } while (0)

    const int lrow = lane & 15;
    const int lcol = (lane >> 4) * 16;

    float acc[4][2][4];
#pragma unroll
    for (int mi = 0; mi < 4; mi++)
#pragma unroll
        for (int ni = 0; ni < 2; ni++)
#pragma unroll
            for (int c = 0; c < 4; c++) acc[mi][ni][c] = 0.0f;

    // prologue
    LOAD_STAGE(0);
    asrc += 128; bsrc += 128;

    for (int kt = 0; kt < NKT; kt++) {
        cp_wait<0>();            // stage kt resident
        __syncthreads();

        if (kt + 1 < NKT) {
            LOAD_STAGE((kt + 1) & 1);   // overlaps with compute below
            asrc += 128; bsrc += 128;
        }

        const uint32_t st = base + (kt & 1) * STAGE_BYTES;
        const uint32_t a_base = st + A_OFF + (wm + lrow) * STRIDE + lcol;
        const uint32_t b_base = st + B_OFF + (wn + lrow) * STRIDE + lcol;

        uint32_t hacc[4][2][2];       // f16x2 accumulators, live for K=32 chunks

#pragma unroll
        for (int ks = 0; ks < 4; ks++) {            // four k16 sub-steps
            uint32_t a[4][4];
#pragma unroll
            for (int mi = 0; mi < 4; mi++)
                ldsm4(a[mi], a_base + mi * 16 * STRIDE + ks * 32);

            uint32_t t4[4];                          // n16 x k16 -> two n8 frags
            ldsm4(t4, b_base + ks * 32);
            uint32_t b0[2] = {t4[0], t4[2]};
            uint32_t b1[2] = {t4[1], t4[3]};

            if ((ks & 1) == 0) {                     // start a K=32 f16 chunk
#pragma unroll
                for (int mi = 0; mi < 4; mi++) {
                    hacc[mi][0][0] = 0u; hacc[mi][0][1] = 0u;
                    hacc[mi][1][0] = 0u; hacc[mi][1][1] = 0u;
                }
            }

#pragma unroll
            for (int mi = 0; mi < 4; mi++) {
                mma16816_h(hacc[mi][0], a[mi], b0);
                mma16816_h(hacc[mi][1], a[mi], b1);
            }

            if (ks & 1) {                            // drain chunk into fp32
#pragma unroll
                for (int mi = 0; mi < 4; mi++)
#pragma unroll
                    for (int ni = 0; ni < 2; ni++) {
                        __half2 p0 = *reinterpret_cast<__half2*>(&hacc[mi][ni][0]);
                        __half2 p1 = *reinterpret_cast<__half2*>(&hacc[mi][ni][1]);
                        acc[mi][ni][0] += __low2float(p0);
                        acc[mi][ni][1] += __high2float(p0);
                        acc[mi][ni][2] += __low2float(p1);
                        acc[mi][ni][3] += __high2float(p1);
                    }
            }
        }
        __syncthreads();         // laggards finish reading slot kt&1 before refill
    }

    // ---------------- epilogue: y = acc * scale + bias ----------------
    const float sc = __ldg(scale);
    const int r0 = lane >> 2;
    const int c0 = 2 * (lane & 3);

#pragma unroll
    for (int ni = 0; ni < 2; ni++) {
        const int col = gn0 + wn + ni * 8 + c0;
        const float2 bv = *reinterpret_cast<const float2*>(bias + col);
#pragma unroll
        for (int mi = 0; mi < 4; mi++) {
            const int row = gm0 + wm + mi * 16 + r0;
            float2 o0, o1;
            o0.x = acc[mi][ni][0] * sc + bv.x;
            o0.y = acc[mi][ni][1] * sc + bv.y;
            o1.x = acc[mi][ni][2] * sc + bv.x;
            o1.y = acc[mi][ni][3] * sc + bv.y;
            *reinterpret_cast<float2*>(out + (size_t)row * DOUT + col)       = o0;
            *reinterpret_cast<float2*>(out + (size_t)(row + 8) * DOUT + col) = o1;
        }
    }
}

// ---------------- launch ----------------
extern "C" void kernel_launch(void* const* d_in, const int* in_sizes, int n_in,
                              void* d_out, int out_size) {
    const float* x     = (const float*)d_in[0];
    const float* w     = (const float*)d_in[1];
    const float* bias  = (const float*)d_in[2];
    const float* scale = (const float*)d_in[3];
    float* out = (float*)d_out;

    convert_all_kernel<<<(XN4 + WN4) / 256, 256>>>((const float4*)x, (const float4*)w);

    cudaFuncSetAttribute(gemm_kernel, cudaFuncAttributeMaxDynamicSharedMemorySize, SMEM_BYTES);
    dim3 grid(DOUT / BN, TOKENS / BM);   // (64, 64)
    gemm_kernel<<<grid, NTHREADS, SMEM_BYTES>>>(bias, scale, out);
}

// round 8
// speedup vs baseline: 4.1458x; 1.2924x over previous
#include <cuda_runtime.h>
#include <cuda_fp16.h>
#include <cstdint>

// ---------------- problem constants ----------------
#define TOKENS 8192
#define DIN    4096
#define DOUT   4096

// ---------------- GEMM tiling ----------------
#define BM 128                 // CTA tile M
#define BN 64                  // CTA tile N
#define BK 64                  // fp16 elements per K stage (128B per row)
#define NKT (DIN / BK)         // 64 K iterations
#define NTHREADS 256           // 8 warps: 2 (m) x 4 (n), warp tile 64x16

// SMEM row stride: 128B data + 16B pad = 144B -> ldmatrix phases conflict-free.
#define STRIDE 144
#define A_OFF 0
#define A_BYTES (BM * STRIDE)            // 18432
#define B_OFF A_BYTES
#define B_BYTES (BN * STRIDE)            // 9216
#define STAGE_BYTES (A_BYTES + B_BYTES)  // 27648
#define SMEM_BYTES (2 * STAGE_BYTES)     // 55296 -> 3 CTAs/SM (166KB < 228KB)

// ---------------- device scratch ----------------
__device__ __half g_w[(size_t)DOUT   * DIN];   // 32 MB; codes 0..126 EXACT in fp16
__device__ __half g_x[(size_t)TOKENS * DIN];   // 64 MB; rel err <= 2^-11/element

// ---------------- PTX helpers ----------------
__device__ __forceinline__ uint32_t smem_u32(const void* p) {
    return (uint32_t)__cvta_generic_to_shared(p);
}
__device__ __forceinline__ void cp16(uint32_t s, const void* g) {
    asm volatile("cp.async.cg.shared.global [%0], [%1], 16;" :: "r"(s), "l"(g));
}
__device__ __forceinline__ void cp_commit() {
    asm volatile("cp.async.commit_group;" ::: "memory");
}
template <int N>
__device__ __forceinline__ void cp_wait() {
    asm volatile("cp.async.wait_group %0;" :: "n"(N) : "memory");
}
__device__ __forceinline__ void ldsm4(uint32_t* r, uint32_t addr) {
    asm volatile("ldmatrix.sync.aligned.m8n8.x4.shared.b16 {%0,%1,%2,%3}, [%4];"
                 : "=r"(r[0]), "=r"(r[1]), "=r"(r[2]), "=r"(r[3]) : "r"(addr));
}
__device__ __forceinline__ void mma16816(float* d, const uint32_t* a, const uint32_t* b) {
    asm volatile(
        "mma.sync.aligned.m16n8k16.row.col.f32.f16.f16.f32 "
        "{%0,%1,%2,%3}, {%4,%5,%6,%7}, {%8,%9}, {%0,%1,%2,%3};"
        : "+f"(d[0]), "+f"(d[1]), "+f"(d[2]), "+f"(d[3])
        : "r"(a[0]), "r"(a[1]), "r"(a[2]), "r"(a[3]), "r"(b[0]), "r"(b[1]));
}
// streaming 8B store (don't pollute L2 with data read exactly once per tile band)
__device__ __forceinline__ void st_cs8(void* p, uint2 v) {
    asm volatile("st.global.cs.v2.u32 [%0], {%1, %2};" :: "l"(p), "r"(v.x), "r"(v.y));
}

// ---------------- fused conversion kernel ----------------
#define XN4 (TOKENS * DIN / 4)
#define WN4 (DOUT * DIN / 4)

__global__ void convert_all_kernel(const float4* __restrict__ x,
                                   const float4* __restrict__ w) {
    int i = blockIdx.x * blockDim.x + threadIdx.x;
    if (i < XN4) {
        float4 v = x[i];
        __half2 p0 = __floats2half2_rn(v.x, v.y);
        __half2 p1 = __floats2half2_rn(v.z, v.w);
        uint2 pk;
        pk.x = *reinterpret_cast<uint32_t*>(&p0);
        pk.y = *reinterpret_cast<uint32_t*>(&p1);
        st_cs8(reinterpret_cast<uint2*>(g_x) + i, pk);
    } else {
        int j = i - XN4;
        float4 v = w[j];
        __half2 p0 = __floats2half2_rn(v.x, v.y);   // exact: integer codes 0..126
        __half2 p1 = __floats2half2_rn(v.z, v.w);
        uint2 pk;
        pk.x = *reinterpret_cast<uint32_t*>(&p0);
        pk.y = *reinterpret_cast<uint32_t*>(&p1);
        st_cs8(reinterpret_cast<uint2*>(g_w) + j, pk);
    }
}

// ---------------- main GEMM ----------------
__global__ void __launch_bounds__(NTHREADS, 3)
gemm_kernel(const float* __restrict__ bias, const float* __restrict__ scale,
            float* __restrict__ out) {
    extern __shared__ char dsm[];
    const uint32_t base = smem_u32(dsm);

    const int tid  = threadIdx.x;
    const int lane = tid & 31;
    const int wrp  = tid >> 5;                 // 8 warps: 2 (m) x 4 (n)
    const int wm   = (wrp >> 2) * 64;          // warp m offset (0/64)
    const int wn   = (wrp & 3) * 16;           // warp n offset (0/16/32/48)
    const int gn0  = blockIdx.x * BN;
    const int gm0  = blockIdx.y * BM;

    // ---- per-thread cp.async state (advance src by 128B per stage) ----
    const int lrowc = tid >> 3;
    const int lseg  = tid & 7;
    const char* asrc = (const char*)(g_x + (size_t)(gm0 + lrowc) * DIN + lseg * 8);
    const char* bsrc = (const char*)(g_w + (size_t)(gn0 + lrowc) * DIN + lseg * 8);
    const uint32_t adst = base + A_OFF + lrowc * STRIDE + lseg * 16;
    const uint32_t bdst = base + B_OFF + lrowc * STRIDE + lseg * 16;

    #define LOAD_STAGE(slot)                                                        \
        do {                                                                        \
            const uint32_t so = (slot) * STAGE_BYTES;                               \
            _Pragma("unroll")                                                       \
            for (int t = 0; t < 4; t++)                                             \
                cp16(adst + so + t * (32 * STRIDE),                                 \
                     asrc + (size_t)t * (32 * DIN * 2));                            \
            _Pragma("unroll")                                                       \
            for (int t = 0; t < 2; t++)                                             \
                cp16(bdst + so + t * (32 * STRIDE),                                 \
                     bsrc + (size_t)t * (32 * DIN * 2));                            \
            cp_commit();                                                            \
        } while (0)

    const int lrow = lane & 15;
    const int lcol = (lane >> 4) * 16;

    float acc[4][2][4];
#pragma unroll
    for (int mi = 0; mi < 4; mi++)
#pragma unroll
        for (int ni = 0; ni < 2; ni++)
#pragma unroll
            for (int c = 0; c < 4; c++) acc[mi][ni][c] = 0.0f;

    // prologue
    LOAD_STAGE(0);
    asrc += 128; bsrc += 128;

    for (int kt = 0; kt < NKT; kt++) {
        cp_wait<0>();            // stage kt resident
        // Barrier orders: (a) this stage's data visible to all warps,
        // (b) all warps finished reading slot (kt+1)&1 in iter kt-1 -> safe to
        //     overwrite it below. The former trailing barrier was redundant.
        __syncthreads();

        if (kt + 1 < NKT) {
            LOAD_STAGE((kt + 1) & 1);   // overlaps with compute below
            asrc += 128; bsrc += 128;
        }

        const uint32_t st = base + (kt & 1) * STAGE_BYTES;
        const uint32_t a_base = st + A_OFF + (wm + lrow) * STRIDE + lcol;
        const uint32_t b_base = st + B_OFF + (wn + lrow) * STRIDE + lcol;

#pragma unroll
        for (int ks = 0; ks < 4; ks++) {            // four k16 sub-steps
            uint32_t a[4][4];
#pragma unroll
            for (int mi = 0; mi < 4; mi++)
                ldsm4(a[mi], a_base + mi * 16 * STRIDE + ks * 32);

            uint32_t t4[4];                          // n16 x k16 -> two n8 frags
            ldsm4(t4, b_base + ks * 32);
            uint32_t b0[2] = {t4[0], t4[2]};
            uint32_t b1[2] = {t4[1], t4[3]};

#pragma unroll
            for (int mi = 0; mi < 4; mi++) {
                mma16816(acc[mi][0], a[mi], b0);
                mma16816(acc[mi][1], a[mi], b1);
            }
        }
    }

    // ---------------- epilogue: y = acc * scale + bias ----------------
    const float sc = __ldg(scale);
    const int r0 = lane >> 2;
    const int c0 = 2 * (lane & 3);

#pragma unroll
    for (int ni = 0; ni < 2; ni++) {
        const int col = gn0 + wn + ni * 8 + c0;
        const float2 bv = *reinterpret_cast<const float2*>(bias + col);
#pragma unroll
        for (int mi = 0; mi < 4; mi++) {
            const int row = gm0 + wm + mi * 16 + r0;
            float2 o0, o1;
            o0.x = acc[mi][ni][0] * sc + bv.x;
            o0.y = acc[mi][ni][1] * sc + bv.y;
            o1.x = acc[mi][ni][2] * sc + bv.x;
            o1.y = acc[mi][ni][3] * sc + bv.y;
            *reinterpret_cast<float2*>(out + (size_t)row * DOUT + col)       = o0;
            *reinterpret_cast<float2*>(out + (size_t)(row + 8) * DOUT + col) = o1;
        }
    }
}

// ---------------- launch ----------------
extern "C" void kernel_launch(void* const* d_in, const int* in_sizes, int n_in,
                              void* d_out, int out_size) {
    const float* x     = (const float*)d_in[0];
    const float* w     = (const float*)d_in[1];
    const float* bias  = (const float*)d_in[2];
    const float* scale = (const float*)d_in[3];
    float* out = (float*)d_out;

    convert_all_kernel<<<(XN4 + WN4) / 256, 256>>>((const float4*)x, (const float4*)w);

    cudaFuncSetAttribute(gemm_kernel, cudaFuncAttributeMaxDynamicSharedMemorySize, SMEM_BYTES);
    dim3 grid(DOUT / BN, TOKENS / BM);   // (64, 64)
    gemm_kernel<<<grid, NTHREADS, SMEM_BYTES>>>(bias, scale, out);
}